// round 16
// baseline (speedup 1.0000x reference)
#include <cuda_runtime.h>
#include <math.h>
#include <stdint.h>

#define Bn 16
#define Cn 256
#define Hn 128
#define Wn 128
#define TH 16
#define TW 16
#define KC 4
#define PAD 4
#define NTHREADS 192
#define HR 24                 // TH + 8 halo rows
#define HCS 48                // smem row stride (floats): conflict-free, 16B-aligned
#define SRC_BUF_B (KC*HR*HCS*4)   // 18432 B per buffer
#define TGT_BUF_B (KC*TH*TW*4)    //  4096 B per buffer
#define HW (Hn*Wn)
#define NS4 3
#define NT4 2
#define T_F4 256

#define GRIDN 296             // 148 SMs x 2 blocks (persistent workers)
#define NTILE 1024            // 16 batches x 8 x 8 tiles of 16x16
#define NITEM 2048            // (tile, C-half) items, strided over workers

__device__ float    g_part[NTILE * 81 * 256];   // per-tile partial sums (BSS zero; finisher re-zeros)
__device__ unsigned g_cnt[NTILE];               // rendezvous counters (finisher resets)

__device__ __forceinline__ void cp16(uint32_t dst, const void* gsrc, int srcsize) {
    asm volatile("cp.async.cg.shared.global [%0], [%1], 16, %2;"
                 :: "r"(dst), "l"(gsrc), "r"(srcsize));
}
__device__ __forceinline__ void cp_commit() {
    asm volatile("cp.async.commit_group;" ::: "memory");
}
__device__ __forceinline__ void cp_wait0() {
    asm volatile("cp.async.wait_group 0;" ::: "memory");
}

__global__ __launch_bounds__(NTHREADS, 2)
void corr_norm_kernel(const float* __restrict__ src,
                      const float* __restrict__ tgt,
                      float* __restrict__ out)
{
    __shared__ __align__(16) float s_src[2][KC][HR][HCS];
    __shared__ __align__(16) float s_tgt[2][KC][TH][TW];
    __shared__ unsigned s_old;

    const int tx  = threadIdx.x;           // 0..3
    const int ty  = threadIdx.y;           // 0..15
    const int tz  = threadIdx.z;           // 0..2
    const int tid = tx + 4 * ty + 64 * tz;

    const uint32_t s_base = (uint32_t)__cvta_generic_to_shared(&s_src[0][0][0][0]);
    const uint32_t t_base = (uint32_t)__cvta_generic_to_shared(&s_tgt[0][0][0][0]);

    // tile-invariant pieces of the cp.async slot decode
    int sc_cc[NS4], sc_r[NS4], sc_c4[NS4]; uint32_t s_dst[NS4];
#pragma unroll
    for (int i = 0; i < NS4; i++) {
        int g4 = tid + i * NTHREADS;           // 0..575
        sc_cc[i] = g4 / (HR * 6);
        int rem  = g4 % (HR * 6);
        sc_r[i]  = rem / 6;
        sc_c4[i] = rem % 6;
        s_dst[i] = s_base + (uint32_t)(((sc_cc[i] * HR + sc_r[i]) * HCS + 4 * sc_c4[i]) * 4);
    }
    int tc_cc[NT4], tc_r[NT4], tc_c4[NT4]; bool t_in[NT4]; uint32_t t_dst[NT4];
#pragma unroll
    for (int i = 0; i < NT4; i++) {
        int g4  = tid + i * NTHREADS;
        t_in[i] = g4 < T_F4;
        int gg  = t_in[i] ? g4 : 0;
        tc_cc[i] = gg / (TH * 4);
        int rem  = gg % (TH * 4);
        tc_r[i]  = rem / 4;
        tc_c4[i] = rem % 4;
        t_dst[i] = t_base + (uint32_t)gg * 16u;
    }

    float acc[3][9][4];

    // strided persistent loop: phase k processes items [296k, 296(k+1)) == launch-wave order
    for (int w = blockIdx.x; w < NITEM; w += GRIDN) {
        const int t    = w >> 1;
        const int half = w & 1;
        const int cbeg = half * 128;
        const int cend = cbeg + 128;

        const int b  = t >> 6;
        const int h0 = ((t >> 3) & 7) * TH;
        const int wb = (t & 7) * TW;

        // per-tile slot addressing
        int s_goff[NS4], s_sz[NS4];
#pragma unroll
        for (int i = 0; i < NS4; i++) {
            int gh = h0 - PAD + sc_r[i];
            int gw = wb - PAD + 4 * sc_c4[i];
            bool ok = ((unsigned)gh < (unsigned)Hn) && (gw >= 0) && (gw <= Wn - 4);
            s_sz[i]   = ok ? 16 : 0;
            s_goff[i] = ok ? (((b * Cn + sc_cc[i]) * Hn + gh) * Wn + gw) : 0;
        }
        int t_goff[NT4];
#pragma unroll
        for (int i = 0; i < NT4; i++)
            t_goff[i] = ((b * Cn + tc_cc[i]) * Hn + h0 + tc_r[i]) * Wn + wb + 4 * tc_c4[i];

#define ISSUE_CHUNK(C0, P) do {                                               \
        const float* sp_ = src + (size_t)(C0) * HW;                           \
        const float* tp_ = tgt + (size_t)(C0) * HW;                           \
        _Pragma("unroll")                                                     \
        for (int i = 0; i < NS4; i++)                                         \
            cp16(s_dst[i] + (P) * SRC_BUF_B, sp_ + s_goff[i], s_sz[i]);       \
        _Pragma("unroll")                                                     \
        for (int i = 0; i < NT4; i++)                                         \
            if (t_in[i]) cp16(t_dst[i] + (P) * TGT_BUF_B, tp_ + t_goff[i], 16); \
        cp_commit();                                                          \
    } while (0)

#pragma unroll
        for (int r = 0; r < 3; r++)
#pragma unroll
            for (int dw = 0; dw < 9; dw++)
#pragma unroll
                for (int q = 0; q < 4; q++) acc[r][dw][q] = 0.f;

        __syncthreads();               // protect smem (previous finisher epilogue) from refill
        ISSUE_CHUNK(cbeg, 0);
        cp_wait0();
        __syncthreads();

        int p = 0;
        for (int c0 = cbeg; c0 < cend; c0 += KC) {
            if (c0 + KC < cend) ISSUE_CHUNK(c0 + KC, p ^ 1);
            else                cp_commit();
#pragma unroll
            for (int cc = 0; cc < KC; cc++) {
                float tt[4];
                *(float4*)tt = *(const float4*)&s_tgt[p][cc][ty][tx * 4];
#pragma unroll
                for (int r = 0; r < 3; r++) {
                    const float* wp = &s_src[p][cc][ty + tz * 3 + r][tx * 4];
                    float win[12];
                    *(float4*)&win[0] = *(const float4*)(wp);
                    *(float4*)&win[4] = *(const float4*)(wp + 4);
                    *(float4*)&win[8] = *(const float4*)(wp + 8);
#pragma unroll
                    for (int dw = 0; dw < 9; dw++)
#pragma unroll
                        for (int q = 0; q < 4; q++)
                            acc[r][dw][q] = fmaf(tt[q], win[dw + q], acc[r][dw][q]);
                }
            }
            cp_wait0();
            __syncthreads();
            p ^= 1;
        }

        float (*s_red)[TH][TW] = reinterpret_cast<float (*)[TH][TW]>(&s_src[0][0][0][0]);

#define EPILOGUE() do {                                                       \
        float part[4] = {0.f, 0.f, 0.f, 0.f};                                 \
        _Pragma("unroll")                                                     \
        for (int r = 0; r < 3; r++)                                           \
            _Pragma("unroll")                                                 \
            for (int dw = 0; dw < 9; dw++)                                    \
                _Pragma("unroll")                                             \
                for (int q = 0; q < 4; q++) {                                 \
                    float v = fmaxf(acc[r][dw][q], 0.f);                      \
                    acc[r][dw][q] = v;                                        \
                    part[q] = fmaf(v, v, part[q]);                            \
                }                                                             \
        *(float4*)&s_red[tz][ty][tx * 4] = *(float4*)part;                    \
        __syncthreads();                                                      \
        float inv[4];                                                         \
        _Pragma("unroll")                                                     \
        for (int q = 0; q < 4; q++) {                                         \
            float s = s_red[0][ty][tx * 4 + q]                                \
                    + s_red[1][ty][tx * 4 + q]                                \
                    + s_red[2][ty][tx * 4 + q];                               \
            inv[q] = 1.f / fmaxf(sqrtf(s), 1e-12f);                           \
        }                                                                     \
        const int h_ = h0 + ty;                                               \
        const int w_ = wb + tx * 4;                                           \
        _Pragma("unroll")                                                     \
        for (int r = 0; r < 3; r++) {                                         \
            int dh_ = tz * 3 + r;                                             \
            _Pragma("unroll")                                                 \
            for (int dw = 0; dw < 9; dw++) {                                  \
                int d_ = dh_ * 9 + dw;                                        \
                float4 o;                                                     \
                o.x = acc[r][dw][0] * inv[0];                                 \
                o.y = acc[r][dw][1] * inv[1];                                 \
                o.z = acc[r][dw][2] * inv[2];                                 \
                o.w = acc[r][dw][3] * inv[3];                                 \
                *(float4*)&out[(((size_t)b * 81 + d_) * Hn + h_) * Wn + w_] = o; \
            }                                                                 \
        }                                                                     \
    } while (0)

        // merge via scratch rendezvous (both halves at same phase -> L2-resident)
        float* gp = g_part + (size_t)t * 81 * 256;
        const int px = ty * TW + tx * 4;
#pragma unroll
        for (int r = 0; r < 3; r++) {
#pragma unroll
            for (int dw = 0; dw < 9; dw++) {
                int d = (tz * 3 + r) * 9 + dw;
#pragma unroll
                for (int q = 0; q < 4; q++)
                    atomicAdd(&gp[d * 256 + px + q], acc[r][dw][q]);
            }
        }
        __threadfence();
        __syncthreads();
        if (tid == 0) s_old = atomicAdd(&g_cnt[t], 1u);
        __syncthreads();
        if (s_old == 1u) {
            // second arriver: both partials present; finish the tile
            __threadfence();
#pragma unroll
            for (int r = 0; r < 3; r++) {
#pragma unroll
                for (int dw = 0; dw < 9; dw++) {
                    int d = (tz * 3 + r) * 9 + dw;
#pragma unroll
                    for (int q = 0; q < 4; q++) {
                        acc[r][dw][q] = gp[d * 256 + px + q];
                        gp[d * 256 + px + q] = 0.f;   // restore for next replay
                    }
                }
            }
            if (tid == 0) g_cnt[t] = 0u;              // restore counter
            EPILOGUE();
        }
    }
}

extern "C" void kernel_launch(void* const* d_in, const int* in_sizes, int n_in,
                              void* d_out, int out_size)
{
    const float* src = (const float*)d_in[0];   // feature_source [16,256,128,128]
    const float* tgt = (const float*)d_in[1];   // feature_target [16,256,128,128]
    float* out = (float*)d_out;                 // [16,81,128,128]

    dim3 grid(GRIDN, 1, 1);                     // persistent: 296 blocks = 148 SMs x 2
    dim3 block(4, TH, 3);                       // 192 threads
    corr_norm_kernel<<<grid, block>>>(src, tgt, out);
}

// round 17
// speedup vs baseline: 1.5883x; 1.5883x over previous
#include <cuda_runtime.h>
#include <math.h>
#include <stdint.h>

#define Bn 16
#define Cn 256
#define Hn 128
#define Wn 128
#define TH 16
#define TW 16
#define KC 4
#define PAD 4
#define NTHREADS 192
#define HR 24                 // TH + 8 halo rows
#define HCS 48                // smem row stride (floats): conflict-free, 16B-aligned
#define SRC_BUF_B (KC*HR*HCS*4)   // 18432 B per buffer
#define TGT_BUF_B (KC*TH*TW*4)    //  4096 B per buffer
#define HW (Hn*Wn)
#define NS4 3
#define NT4 2
#define T_F4 256

#define SPLIT 888             // 3 x 296 = three exact full waves at occ 2

__device__ __forceinline__ void cp16(uint32_t dst, const void* gsrc, int srcsize) {
    asm volatile("cp.async.cg.shared.global [%0], [%1], 16, %2;"
                 :: "r"(dst), "l"(gsrc), "r"(srcsize));
}
__device__ __forceinline__ void cp_commit() {
    asm volatile("cp.async.commit_group;" ::: "memory");
}
__device__ __forceinline__ void cp_wait0() {
    asm volatile("cp.async.wait_group 0;" ::: "memory");
}

__global__ __launch_bounds__(NTHREADS, 2)
void corr_norm_kernel(const float* __restrict__ src,
                      const float* __restrict__ tgt,
                      float* __restrict__ out,
                      int tile_base)
{
    __shared__ __align__(16) float s_src[2][KC][HR][HCS];
    __shared__ __align__(16) float s_tgt[2][KC][TH][TW];

    const int tx  = threadIdx.x;           // 0..3  : 4-px groups along w
    const int ty  = threadIdx.y;           // 0..15 : h within tile
    const int tz  = threadIdx.z;           // 0..2  : dh group (3 rows each)
    const int tid = tx + 4 * ty + 64 * tz;

    // 1D tile decode, same order as R14's (w,h,b) grid: w fastest
    const int t  = tile_base + blockIdx.x;
    const int b  = t >> 6;
    const int h0 = ((t >> 3) & 7) * TH;
    const int wb = (t & 7) * TW;

    const uint32_t s_base = (uint32_t)__cvta_generic_to_shared(&s_src[0][0][0][0]);
    const uint32_t t_base = (uint32_t)__cvta_generic_to_shared(&s_tgt[0][0][0][0]);

    // ---- f4 cp.async slot addressing (invariant across chunks) ----
    int s_goff[NS4]; int s_sz[NS4]; uint32_t s_dst[NS4];
#pragma unroll
    for (int i = 0; i < NS4; i++) {
        int g4  = tid + i * NTHREADS;          // 0..575, exact fit
        int cc  = g4 / (HR * 6);
        int rem = g4 % (HR * 6);
        int r   = rem / 6;
        int c4  = rem % 6;
        int gh  = h0 - PAD + r;
        int gw  = wb - PAD + 4 * c4;
        bool ok = ((unsigned)gh < (unsigned)Hn) && (gw >= 0) && (gw <= Wn - 4);
        s_sz[i]   = ok ? 16 : 0;
        s_goff[i] = ok ? (((b * Cn + cc) * Hn + gh) * Wn + gw) : 0;
        s_dst[i]  = s_base + (uint32_t)(((cc * HR + r) * HCS + 4 * c4) * 4);
    }
    int t_goff[NT4]; bool t_in[NT4]; uint32_t t_dst[NT4];
#pragma unroll
    for (int i = 0; i < NT4; i++) {
        int g4  = tid + i * NTHREADS;
        t_in[i] = g4 < T_F4;
        int gg  = t_in[i] ? g4 : 0;
        int cc  = gg / (TH * 4);
        int rem = gg % (TH * 4);
        int r   = rem / 4;
        int c4  = rem % 4;
        t_goff[i] = ((b * Cn + cc) * Hn + h0 + r) * Wn + wb + 4 * c4;
        t_dst[i]  = t_base + (uint32_t)gg * 16u;
    }

#define ISSUE_CHUNK(C0, P) do {                                               \
        const float* sp_ = src + (size_t)(C0) * HW;                           \
        const float* tp_ = tgt + (size_t)(C0) * HW;                           \
        _Pragma("unroll")                                                     \
        for (int i = 0; i < NS4; i++)                                         \
            cp16(s_dst[i] + (P) * SRC_BUF_B, sp_ + s_goff[i], s_sz[i]);       \
        _Pragma("unroll")                                                     \
        for (int i = 0; i < NT4; i++)                                         \
            if (t_in[i]) cp16(t_dst[i] + (P) * TGT_BUF_B, tp_ + t_goff[i], 16); \
        cp_commit();                                                          \
    } while (0)

    // ---- accumulators: 3 dh rows x 9 dw x 4 pixels = 108 fp32 ----
    float acc[3][9][4];
#pragma unroll
    for (int r = 0; r < 3; r++)
#pragma unroll
        for (int dw = 0; dw < 9; dw++)
#pragma unroll
            for (int p = 0; p < 4; p++) acc[r][dw][p] = 0.f;

    // prologue: fill buffer 0 with chunk 0
    ISSUE_CHUNK(0, 0);
    cp_wait0();
    __syncthreads();

    int p = 0;
    for (int c0 = 0; c0 < Cn; c0 += KC) {
        if (c0 + KC < Cn) ISSUE_CHUNK(c0 + KC, p ^ 1);
        else              cp_commit();   // keep group count consistent

        // compute chunk c0 from buffer p (proven FFMA-saturated core)
#pragma unroll
        for (int cc = 0; cc < KC; cc++) {
            float tt[4];
            *(float4*)tt = *(const float4*)&s_tgt[p][cc][ty][tx * 4];
#pragma unroll
            for (int r = 0; r < 3; r++) {
                const float* wp = &s_src[p][cc][ty + tz * 3 + r][tx * 4];
                float win[12];
                *(float4*)&win[0] = *(const float4*)(wp);
                *(float4*)&win[4] = *(const float4*)(wp + 4);
                *(float4*)&win[8] = *(const float4*)(wp + 8);
#pragma unroll
                for (int dw = 0; dw < 9; dw++)
#pragma unroll
                    for (int q = 0; q < 4; q++)
                        acc[r][dw][q] = fmaf(tt[q], win[dw + q], acc[r][dw][q]);
            }
        }

        cp_wait0();
        __syncthreads();
        p ^= 1;
    }

    // ---- fused relu + L2-normalize over the 81 displacement channels ----
    float (*s_red)[TH][TW] = reinterpret_cast<float (*)[TH][TW]>(&s_src[0][0][0][0]);

    float part[4] = {0.f, 0.f, 0.f, 0.f};
#pragma unroll
    for (int r = 0; r < 3; r++)
#pragma unroll
        for (int dw = 0; dw < 9; dw++)
#pragma unroll
            for (int q = 0; q < 4; q++) {
                float v = fmaxf(acc[r][dw][q], 0.f);
                acc[r][dw][q] = v;
                part[q] = fmaf(v, v, part[q]);
            }
    *(float4*)&s_red[tz][ty][tx * 4] = *(float4*)part;
    __syncthreads();

    float inv[4];
#pragma unroll
    for (int q = 0; q < 4; q++) {
        float s = s_red[0][ty][tx * 4 + q]
                + s_red[1][ty][tx * 4 + q]
                + s_red[2][ty][tx * 4 + q];
        inv[q] = 1.f / fmaxf(sqrtf(s), 1e-12f);
    }

    const int h = h0 + ty;
    const int w = wb + tx * 4;
#pragma unroll
    for (int r = 0; r < 3; r++) {
        int dh = tz * 3 + r;
#pragma unroll
        for (int dw = 0; dw < 9; dw++) {
            int d = dh * 9 + dw;
            float4 o;
            o.x = acc[r][dw][0] * inv[0];
            o.y = acc[r][dw][1] * inv[1];
            o.z = acc[r][dw][2] * inv[2];
            o.w = acc[r][dw][3] * inv[3];
            *(float4*)&out[(((size_t)b * 81 + d) * Hn + h) * Wn + w] = o;
        }
    }
}

extern "C" void kernel_launch(void* const* d_in, const int* in_sizes, int n_in,
                              void* d_out, int out_size)
{
    const float* src = (const float*)d_in[0];   // feature_source [16,256,128,128]
    const float* tgt = (const float*)d_in[1];   // feature_target [16,256,128,128]
    float* out = (float*)d_out;                 // [16,81,128,128]

    dim3 block(4, TH, 3);                       // 192 threads

    // Launch A: 888 blocks = exactly 3 full waves at 2 blocks/SM (chip saturated)
    corr_norm_kernel<<<dim3(SPLIT, 1, 1), block>>>(src, tgt, out, 0);
    // Launch B: 136 blocks, <=1 per SM -> lone blocks saturate their SM's FFMA
    // pipe alone and drain the tail at ~2x shared-wave speed
    corr_norm_kernel<<<dim3(1024 - SPLIT, 1, 1), block>>>(src, tgt, out, SPLIT);
}